// round 4
// baseline (speedup 1.0000x reference)
#include <cuda_runtime.h>
#include <math.h>

#define OFFD 131

__device__ float g_qH[512*128*32];
__device__ float g_kH[512*128*32];
__device__ float g_qW[512*128*32];
__device__ float g_kW[512*128*32];
__device__ float g_vH[512*128*256];
__device__ float g_vW[512*128*256];
__device__ float g_p0[128*128*320];
__device__ float g_EH[512*128*128];
__device__ float g_EW[512*128*128];
__device__ float g_cO[512*128*256];
__device__ float g_rO[512*128*256];
__device__ float g_dX[129][2];
__device__ float g_dY[129][2];

// ---- offset pooling + regloss ----
__global__ void kern_prep(const float* __restrict__ off, float* __restrict__ out, int regIdx)
{
    const int t = threadIdx.x;
    const float inv9 = 1.0f / 9.0f;
    for (int idx = t; idx < 258; idx += 512) {
        int r = idx % 129, ch = idx / 129;
        const float* o = off + ch * OFFD * OFFD;
        float s = 0.f;
        #pragma unroll
        for (int i = 0; i < 3; i++)
            #pragma unroll
            for (int j = 0; j < 3; j++) s += o[(r + i) * OFFD + 64 + j];
        g_dX[r][ch] = s * inv9;
    }
    for (int idx = t; idx < 258; idx += 512) {
        int c = idx % 129, ch = idx / 129;
        const float* o = off + ch * OFFD * OFFD;
        float s = 0.f;
        #pragma unroll
        for (int i = 0; i < 3; i++)
            #pragma unroll
            for (int j = 0; j < 3; j++) s += o[(64 + i) * OFFD + c + j];
        g_dY[c][ch] = s * inv9;
    }
    float s1 = 0.f, s2 = 0.f;
    for (int i = t; i < OFFD * OFFD; i += 512) {
        float d = off[i] - off[OFFD * OFFD + i];
        s1 += d * d;
    }
    for (int i = t; i < 2 * 130 * OFFD; i += 512) {
        int ch = i / (130 * OFFD);
        int rem = i - ch * 130 * OFFD;
        int r = rem / OFFD, c = rem - r * OFFD;
        float d = off[ch * OFFD * OFFD + r * OFFD + c] - off[ch * OFFD * OFFD + (r + 1) * OFFD + c];
        s2 += d * d;
    }
    __shared__ float sh1[512], sh2[512];
    sh1[t] = s1; sh2[t] = s2;
    __syncthreads();
    for (int s = 256; s > 0; s >>= 1) {
        if (t < s) { sh1[t] += sh1[t + s]; sh2[t] += sh2[t + s]; }
        __syncthreads();
    }
    if (t == 0)
        out[regIdx] = sh1[0] / (float)(OFFD * OFFD) + sh2[0] / (float)(2 * 130 * OFFD);
}

// ---- fused QKV projection GEMM: grid (h=128, otile=5, b=4), block 256 ----
__global__ __launch_bounds__(256) void kern_proj(
    const float* __restrict__ x,
    const float* __restrict__ Wq, const float* __restrict__ bq,
    const float* __restrict__ Wk, const float* __restrict__ bk,
    const float* __restrict__ Wv, const float* __restrict__ bv)
{
    __shared__ __align__(16) float sm[8704];
    float (*Xs)[132] = (float (*)[132])sm;
    float (*Wt)[68]  = (float (*)[68])(sm + 32 * 132);
    float (*Ot)[68]  = (float (*)[68])sm;

    const int h = blockIdx.x, ot = blockIdx.y, b = blockIdx.z;
    const int t = threadIdx.x;
    const int tw = t & 15, to = t >> 4;
    const int o0 = ot * 64;

    float acc[4][8];
    #pragma unroll
    for (int j = 0; j < 4; j++)
        #pragma unroll
        for (int i = 0; i < 8; i++) acc[j][i] = 0.f;

    const float* xb = x + ((size_t)b * 256) * 16384 + (size_t)h * 128;

    for (int kc = 0; kc < 8; kc++) {
        const int c0 = kc * 32;
        #pragma unroll
        for (int r = 0; r < 4; r++) {
            int lin = t + r * 256;
            int row = lin >> 5, col = (lin & 31) << 2;
            *(float4*)&Xs[row][col] = *(const float4*)(xb + (size_t)(c0 + row) * 16384 + col);
        }
        #pragma unroll
        for (int r = 0; r < 2; r++) {
            int lin = t + r * 256;
            int oo = lin >> 3, cc = (lin & 7) << 2;
            int o = o0 + oo;
            const float* wrow = (o < 32) ? (Wq + (size_t)o * 256)
                               : (o < 64) ? (Wk + (size_t)(o - 32) * 256)
                                          : (Wv + (size_t)(o - 64) * 256);
            float4 v = *(const float4*)(wrow + c0 + cc);
            Wt[cc][oo] = v.x; Wt[cc + 1][oo] = v.y; Wt[cc + 2][oo] = v.z; Wt[cc + 3][oo] = v.w;
        }
        __syncthreads();
        #pragma unroll
        for (int cc = 0; cc < 32; cc++) {
            float4 xa = *(const float4*)&Xs[cc][tw * 8];
            float4 xb4 = *(const float4*)&Xs[cc][tw * 8 + 4];
            float4 wv = *(const float4*)&Wt[cc][to * 4];
            float xr[8] = {xa.x, xa.y, xa.z, xa.w, xb4.x, xb4.y, xb4.z, xb4.w};
            float wr[4] = {wv.x, wv.y, wv.z, wv.w};
            #pragma unroll
            for (int j = 0; j < 4; j++)
                #pragma unroll
                for (int i = 0; i < 8; i++) acc[j][i] += wr[j] * xr[i];
        }
        __syncthreads();
    }

    #pragma unroll
    for (int j = 0; j < 4; j++) {
        int o = o0 + to * 4 + j;
        float bs = (o < 32) ? bq[o] : (o < 64) ? bk[o - 32] : bv[o - 64];
        #pragma unroll
        for (int i = 0; i < 8; i++) Ot[tw * 8 + i][to * 4 + j] = acc[j][i] + bs;
    }
    __syncthreads();

    if (ot == 0) {
        int w = t >> 1, half = t & 1;
        const float* src = &Ot[w][half * 32];
        if (b > 0) {
            float* dst = half ? (g_kH + (((size_t)(b * 128 + w)) * 128 + h) * 32)
                              : (g_qH + (((size_t)(b * 128 + w)) * 128 + h) * 32);
            #pragma unroll
            for (int i = 0; i < 8; i++) ((float4*)dst)[i] = ((const float4*)src)[i];
            float* dq = g_qW + ((size_t)(b * 128 + h)) * 4096;
            float* dk = g_kW + ((size_t)(b * 128 + h)) * 4096;
            #pragma unroll
            for (int r = 0; r < 4; r++) {
                int e = (t + r * 256) << 2;
                int wI = e >> 5, cI = e & 31;
                *(float4*)(dq + e) = *(const float4*)&Ot[wI][cI];
                *(float4*)(dk + e) = *(const float4*)&Ot[wI][32 + cI];
            }
        } else {
            float* dst = g_p0 + ((size_t)(h * 128 + w)) * 320 + half * 32;
            #pragma unroll
            for (int i = 0; i < 8; i++) ((float4*)dst)[i] = ((const float4*)src)[i];
        }
    } else {
        const int c0v = (ot - 1) * 64;
        int w = t >> 1, half = t & 1;
        const float* src = &Ot[w][half * 32];
        if (b > 0) {
            float* dst = g_vH + (((size_t)(b * 128 + w)) * 128 + h) * 256 + c0v + half * 32;
            #pragma unroll
            for (int i = 0; i < 8; i++) ((float4*)dst)[i] = ((const float4*)src)[i];
            float* dw = g_vW + ((size_t)(b * 128 + h)) * 32768 + c0v;
            #pragma unroll
            for (int r = 0; r < 8; r++) {
                int e = (t + r * 256) << 2;
                int wI = e >> 6, cI = e & 63;
                *(float4*)(dw + (size_t)wI * 256 + cI) = *(const float4*)&Ot[wI][cI];
            }
        } else {
            float* dst = g_p0 + ((size_t)(h * 128 + w)) * 320 + 64 + c0v + half * 32;
            #pragma unroll
            for (int i = 0; i < 8; i++) ((float4*)dst)[i] = ((const float4*)src)[i];
        }
    }
}

// ---- deformable bilinear sampling of batch-0 lines: grid (16384, 2), block 320 ----
__global__ void kern_sample()
{
    const int pt = blockIdx.x, br = blockIdx.y;
    const int k = pt >> 7, pos = pt & 127;
    float px, py;
    if (br == 0) {
        int r = pos + 1;
        px = (-1.0f + k * 0.015625f) + g_dX[r][0];
        py = (-1.0f + r * 0.015625f) + g_dX[r][1];
    } else {
        int ci = pos + 1;
        px = (-1.0f + ci * 0.015625f) + g_dY[ci][0];
        py = (-1.0f + k * 0.015625f) + g_dY[ci][1];
    }
    float fx = (px + 1.0f) * 0.5f * 127.0f;
    float fy = (py + 1.0f) * 0.5f * 127.0f;
    float x0f = floorf(fx), y0f = floorf(fy);
    float wx = fx - x0f, wy = fy - y0f;
    int x0 = (int)x0f, y0 = (int)y0f;
    bool vx0 = (x0 >= 0) && (x0 < 128);
    bool vx1 = (x0 + 1 >= 0) && (x0 + 1 < 128);
    bool vy0 = (y0 >= 0) && (y0 < 128);
    bool vy1 = (y0 + 1 >= 0) && (y0 + 1 < 128);

    const int c = threadIdx.x;
    float acc = 0.f;
    if (vx0 && vy0) acc += g_p0[((size_t)(y0 * 128 + x0)) * 320 + c] * ((1.f - wx) * (1.f - wy));
    if (vx1 && vy0) acc += g_p0[((size_t)(y0 * 128 + x0 + 1)) * 320 + c] * (wx * (1.f - wy));
    if (vx0 && vy1) acc += g_p0[((size_t)((y0 + 1) * 128 + x0)) * 320 + c] * ((1.f - wx) * wy);
    if (vx1 && vy1) acc += g_p0[((size_t)((y0 + 1) * 128 + x0 + 1)) * 320 + c] * (wx * wy);

    size_t lp = (size_t)k * 128 + pos;
    if (br == 0) {
        if (c < 32)      g_qH[lp * 32 + c] = acc;
        else if (c < 64) g_kH[lp * 32 + (c - 32)] = acc;
        else             g_vH[lp * 256 + (c - 64)] = acc;
    } else {
        if (c < 32)      g_qW[lp * 32 + c] = acc;
        else if (c < 64) g_kW[lp * 32 + (c - 32)] = acc;
        else             g_vW[lp * 256 + (c - 64)] = acc;
    }
}

// ---- per-line energy GEMM E = Q @ K^T: grid (512, 2), block 256 ----
__global__ __launch_bounds__(256) void kern_energy()
{
    __shared__ __align__(16) float Qt[32][132];
    __shared__ __align__(16) float Kt[32][132];
    const int l = blockIdx.x, br = blockIdx.y;
    const float* Q = (br ? g_qW : g_qH) + (size_t)l * 4096;
    const float* K = (br ? g_kW : g_kH) + (size_t)l * 4096;
    float* E = (br ? g_EW : g_EH) + (size_t)l * 16384;
    const int t = threadIdx.x;

    #pragma unroll
    for (int r = 0; r < 4; r++) {
        int lin = t + r * 256;
        int p = lin >> 3, c4 = (lin & 7) << 2;
        float4 q = *(const float4*)(Q + (size_t)p * 32 + c4);
        Qt[c4][p] = q.x; Qt[c4 + 1][p] = q.y; Qt[c4 + 2][p] = q.z; Qt[c4 + 3][p] = q.w;
        float4 kk = *(const float4*)(K + (size_t)p * 32 + c4);
        Kt[c4][p] = kk.x; Kt[c4 + 1][p] = kk.y; Kt[c4 + 2][p] = kk.z; Kt[c4 + 3][p] = kk.w;
    }
    __syncthreads();

    const int tj = t & 15, ti = t >> 4;
    const int i0 = ti * 8, j0 = tj * 8;
    float acc[8][8];
    #pragma unroll
    for (int u = 0; u < 8; u++)
        #pragma unroll
        for (int v = 0; v < 8; v++) acc[u][v] = 0.f;

    #pragma unroll
    for (int c = 0; c < 32; c++) {
        float4 qa = *(const float4*)&Qt[c][i0];
        float4 qb = *(const float4*)&Qt[c][i0 + 4];
        float4 ka = *(const float4*)&Kt[c][j0];
        float4 kb = *(const float4*)&Kt[c][j0 + 4];
        float q[8] = {qa.x, qa.y, qa.z, qa.w, qb.x, qb.y, qb.z, qb.w};
        float kv[8] = {ka.x, ka.y, ka.z, ka.w, kb.x, kb.y, kb.z, kb.w};
        #pragma unroll
        for (int u = 0; u < 8; u++)
            #pragma unroll
            for (int v = 0; v < 8; v++) acc[u][v] += q[u] * kv[v];
    }
    #pragma unroll
    for (int u = 0; u < 8; u++) {
        *(float4*)(E + (size_t)(i0 + u) * 128 + j0) = make_float4(acc[u][0], acc[u][1], acc[u][2], acc[u][3]);
        *(float4*)(E + (size_t)(i0 + u) * 128 + j0 + 4) = make_float4(acc[u][4], acc[u][5], acc[u][6], acc[u][7]);
    }
}

// ---- joint softmax: one warp per pixel, grid 8192 x 256 ----
__global__ void kern_softmax()
{
    int gw = (blockIdx.x * blockDim.x + threadIdx.x) >> 5;
    int lane = threadIdx.x & 31;
    if (gw >= 65536) return;
    int b = gw >> 14;
    int rem = gw & 16383;
    int h = rem >> 7, w = rem & 127;
    float* r1 = g_EH + (((size_t)(b * 128 + w)) * 128 + h) * 128;
    float* r2 = g_EW + (((size_t)(b * 128 + h)) * 128 + w) * 128;
    float4 a = *(float4*)(r1 + lane * 4);
    float4 c = *(float4*)(r2 + lane * 4);
    float e1[4] = {a.x, a.y, a.z, a.w};
    float e2[4] = {c.x, c.y, c.z, c.w};
    float m = -INFINITY;
    #pragma unroll
    for (int u = 0; u < 4; u++) {
        if (lane * 4 + u != h) m = fmaxf(m, e1[u]);
        m = fmaxf(m, e2[u]);
    }
    #pragma unroll
    for (int s = 16; s > 0; s >>= 1) m = fmaxf(m, __shfl_xor_sync(0xffffffffu, m, s));
    float sum = 0.f;
    #pragma unroll
    for (int u = 0; u < 4; u++) {
        e1[u] = (lane * 4 + u == h) ? 0.f : __expf(e1[u] - m);
        sum += e1[u];
        e2[u] = __expf(e2[u] - m);
        sum += e2[u];
    }
    #pragma unroll
    for (int s = 16; s > 0; s >>= 1) sum += __shfl_xor_sync(0xffffffffu, sum, s);
    float inv = 1.0f / sum;
    *(float4*)(r1 + lane * 4) = make_float4(e1[0] * inv, e1[1] * inv, e1[2] * inv, e1[3] * inv);
    *(float4*)(r2 + lane * 4) = make_float4(e2[0] * inv, e2[1] * inv, e2[2] * inv, e2[3] * inv);
}

// ---- per-line output GEMM O = A @ V: grid (512, 2 chalf, 2 br), block 256 ----
__global__ __launch_bounds__(256) void kern_out()
{
    __shared__ __align__(16) float As[32][132];
    __shared__ __align__(16) float Vs[32][132];
    const int l = blockIdx.x, chf = blockIdx.y, br = blockIdx.z;
    const float* A = (br ? g_EW : g_EH) + (size_t)l * 16384;
    const float* V = (br ? g_vW : g_vH) + (size_t)l * 32768;
    float* O = (br ? g_rO : g_cO) + (size_t)l * 32768 + chf * 128;
    const int t = threadIdx.x;
    const int tj = t & 15, ti = t >> 4;
    const int i0 = ti * 8, j0 = tj * 8;

    float acc[8][8];
    #pragma unroll
    for (int u = 0; u < 8; u++)
        #pragma unroll
        for (int v = 0; v < 8; v++) acc[u][v] = 0.f;

    for (int hc = 0; hc < 4; hc++) {
        #pragma unroll
        for (int r = 0; r < 4; r++) {
            int lin = t + r * 256;
            int k = lin >> 3, h4 = (lin & 7) << 2;
            float4 a = *(const float4*)(A + (size_t)k * 128 + hc * 32 + h4);
            As[h4][k] = a.x; As[h4 + 1][k] = a.y; As[h4 + 2][k] = a.z; As[h4 + 3][k] = a.w;
            int hh = lin >> 5, c4 = (lin & 31) << 2;
            *(float4*)&Vs[hh][c4] = *(const float4*)(V + (size_t)(hc * 32 + hh) * 256 + chf * 128 + c4);
        }
        __syncthreads();
        #pragma unroll
        for (int hh = 0; hh < 32; hh++) {
            float4 aa = *(const float4*)&As[hh][i0];
            float4 ab = *(const float4*)&As[hh][i0 + 4];
            float4 va = *(const float4*)&Vs[hh][j0];
            float4 vb = *(const float4*)&Vs[hh][j0 + 4];
            float ar[8] = {aa.x, aa.y, aa.z, aa.w, ab.x, ab.y, ab.z, ab.w};
            float vr[8] = {va.x, va.y, va.z, va.w, vb.x, vb.y, vb.z, vb.w};
            #pragma unroll
            for (int u = 0; u < 8; u++)
                #pragma unroll
                for (int v = 0; v < 8; v++) acc[u][v] += ar[u] * vr[v];
        }
        __syncthreads();
    }
    #pragma unroll
    for (int u = 0; u < 8; u++) {
        *(float4*)(O + (size_t)(i0 + u) * 256 + j0) = make_float4(acc[u][0], acc[u][1], acc[u][2], acc[u][3]);
        *(float4*)(O + (size_t)(i0 + u) * 256 + j0 + 4) = make_float4(acc[u][4], acc[u][5], acc[u][6], acc[u][7]);
    }
}

// ---- combine: out = gamma*(colO + rowO) + x: grid (128 h, 8 ctile, 4 b), block 256 ----
__global__ void kern_combine(const float* __restrict__ x, const float* __restrict__ gamma,
                             float* __restrict__ out)
{
    __shared__ __align__(16) float s[32][132];
    const int h = blockIdx.x, ct = blockIdx.y, b = blockIdx.z;
    const int c0 = ct * 32, t = threadIdx.x;
    #pragma unroll
    for (int r = 0; r < 4; r++) {
        int lin = t + r * 256;
        int w = lin >> 3, c4 = (lin & 7) << 2;
        float4 a = *(const float4*)(g_cO + (((size_t)(b * 128 + w)) * 128 + h) * 256 + c0 + c4);
        float4 bb = *(const float4*)(g_rO + (((size_t)(b * 128 + h)) * 128 + w) * 256 + c0 + c4);
        s[c4][w] = a.x + bb.x; s[c4 + 1][w] = a.y + bb.y;
        s[c4 + 2][w] = a.z + bb.z; s[c4 + 3][w] = a.w + bb.w;
    }
    __syncthreads();
    float g = gamma[0];
    #pragma unroll
    for (int r = 0; r < 4; r++) {
        int lin = t + r * 256;
        int c = lin >> 5, w4 = (lin & 31) << 2;
        size_t oidx = (((size_t)b * 256 + c0 + c) * 128 + h) * 128 + w4;
        float4 xv = *(const float4*)(x + oidx);
        float4 o;
        o.x = g * s[c][w4] + xv.x;
        o.y = g * s[c][w4 + 1] + xv.y;
        o.z = g * s[c][w4 + 2] + xv.z;
        o.w = g * s[c][w4 + 3] + xv.w;
        *(float4*)(out + oidx) = o;
    }
}

extern "C" void kernel_launch(void* const* d_in, const int* in_sizes, int n_in,
                              void* d_out, int out_size)
{
    const float* x      = (const float*)d_in[0];
    const float* Wq     = (const float*)d_in[1];
    const float* bq     = (const float*)d_in[2];
    const float* Wk     = (const float*)d_in[3];
    const float* bk     = (const float*)d_in[4];
    const float* Wv     = (const float*)d_in[5];
    const float* bv     = (const float*)d_in[6];
    const float* gamma  = (const float*)d_in[7];
    const float* offs   = (const float*)d_in[8];
    float* out = (float*)d_out;

    kern_prep<<<1, 512>>>(offs, out, out_size - 1);
    kern_proj<<<dim3(128, 5, 4), 256>>>(x, Wq, bq, Wk, bk, Wv, bv);
    kern_sample<<<dim3(16384, 2), 320>>>();
    kern_energy<<<dim3(512, 2), 256>>>();
    kern_softmax<<<8192, 256>>>();
    kern_out<<<dim3(512, 2, 2), 256>>>();
    kern_combine<<<dim3(128, 8, 4), 256>>>(x, gamma, out);
}

// round 5
// speedup vs baseline: 1.0032x; 1.0032x over previous
#include <cuda_runtime.h>
#include <math.h>

#define OFFD 131

__device__ float g_qH[512*128*32];
__device__ float g_kH[512*128*32];
__device__ float g_qW[512*128*32];
__device__ float g_kW[512*128*32];
__device__ float g_vH[512*128*256];
__device__ float g_vW[512*128*256];
__device__ float g_p0[128*128*320];
__device__ float g_EH[512*128*128];
__device__ float g_EW[512*128*128];
__device__ float g_cO[512*128*256];
__device__ float g_rO[512*128*256];
__device__ float g_dX[129][2];
__device__ float g_dY[129][2];

typedef unsigned long long ull;

// packed fp32x2 helpers: FFMA2 path (2 FMAs per fma-pipe issue)
__device__ __forceinline__ void ffma2(ull& d, ull a, ull b) {
    asm("fma.rn.f32x2 %0, %1, %2, %0;" : "+l"(d) : "l"(a), "l"(b));
}
__device__ __forceinline__ ull dup2(float x) {
    ull r; asm("mov.b64 %0, {%1, %1};" : "=l"(r) : "f"(x)); return r;
}
__device__ __forceinline__ float2 u2f(ull v) {
    float2 f; asm("mov.b64 {%0, %1}, %2;" : "=f"(f.x), "=f"(f.y) : "l"(v)); return f;
}

// ---- offset pooling + regloss ----
__global__ void kern_prep(const float* __restrict__ off, float* __restrict__ out, int regIdx)
{
    const int t = threadIdx.x;
    const float inv9 = 1.0f / 9.0f;
    for (int idx = t; idx < 258; idx += 512) {
        int r = idx % 129, ch = idx / 129;
        const float* o = off + ch * OFFD * OFFD;
        float s = 0.f;
        #pragma unroll
        for (int i = 0; i < 3; i++)
            #pragma unroll
            for (int j = 0; j < 3; j++) s += o[(r + i) * OFFD + 64 + j];
        g_dX[r][ch] = s * inv9;
    }
    for (int idx = t; idx < 258; idx += 512) {
        int c = idx % 129, ch = idx / 129;
        const float* o = off + ch * OFFD * OFFD;
        float s = 0.f;
        #pragma unroll
        for (int i = 0; i < 3; i++)
            #pragma unroll
            for (int j = 0; j < 3; j++) s += o[(64 + i) * OFFD + c + j];
        g_dY[c][ch] = s * inv9;
    }
    float s1 = 0.f, s2 = 0.f;
    for (int i = t; i < OFFD * OFFD; i += 512) {
        float d = off[i] - off[OFFD * OFFD + i];
        s1 += d * d;
    }
    for (int i = t; i < 2 * 130 * OFFD; i += 512) {
        int ch = i / (130 * OFFD);
        int rem = i - ch * 130 * OFFD;
        int r = rem / OFFD, c = rem - r * OFFD;
        float d = off[ch * OFFD * OFFD + r * OFFD + c] - off[ch * OFFD * OFFD + (r + 1) * OFFD + c];
        s2 += d * d;
    }
    __shared__ float sh1[512], sh2[512];
    sh1[t] = s1; sh2[t] = s2;
    __syncthreads();
    for (int s = 256; s > 0; s >>= 1) {
        if (t < s) { sh1[t] += sh1[t + s]; sh2[t] += sh2[t + s]; }
        __syncthreads();
    }
    if (t == 0)
        out[regIdx] = sh1[0] / (float)(OFFD * OFFD) + sh2[0] / (float)(2 * 130 * OFFD);
}

// ---- fused QKV projection GEMM: grid (h=128, otile=5, b=4), block 256 ----
__global__ __launch_bounds__(256) void kern_proj(
    const float* __restrict__ x,
    const float* __restrict__ Wq, const float* __restrict__ bq,
    const float* __restrict__ Wk, const float* __restrict__ bk,
    const float* __restrict__ Wv, const float* __restrict__ bv)
{
    __shared__ __align__(16) float sm[8704];
    float (*Xs)[132] = (float (*)[132])sm;
    float (*Wt)[68]  = (float (*)[68])(sm + 32 * 132);
    float (*Ot)[68]  = (float (*)[68])sm;

    const int h = blockIdx.x, ot = blockIdx.y, b = blockIdx.z;
    const int t = threadIdx.x;
    const int tw = t & 15, to = t >> 4;
    const int o0 = ot * 64;

    ull acc2[4][4];
    #pragma unroll
    for (int j = 0; j < 4; j++)
        #pragma unroll
        for (int i = 0; i < 4; i++) acc2[j][i] = 0ULL;

    const float* xb = x + ((size_t)b * 256) * 16384 + (size_t)h * 128;

    for (int kc = 0; kc < 8; kc++) {
        const int c0 = kc * 32;
        #pragma unroll
        for (int r = 0; r < 4; r++) {
            int lin = t + r * 256;
            int row = lin >> 5, col = (lin & 31) << 2;
            *(float4*)&Xs[row][col] = *(const float4*)(xb + (size_t)(c0 + row) * 16384 + col);
        }
        #pragma unroll
        for (int r = 0; r < 2; r++) {
            int lin = t + r * 256;
            int oo = lin >> 3, cc = (lin & 7) << 2;
            int o = o0 + oo;
            const float* wrow = (o < 32) ? (Wq + (size_t)o * 256)
                               : (o < 64) ? (Wk + (size_t)(o - 32) * 256)
                                          : (Wv + (size_t)(o - 64) * 256);
            float4 v = *(const float4*)(wrow + c0 + cc);
            Wt[cc][oo] = v.x; Wt[cc + 1][oo] = v.y; Wt[cc + 2][oo] = v.z; Wt[cc + 3][oo] = v.w;
        }
        __syncthreads();
        #pragma unroll
        for (int cc = 0; cc < 32; cc++) {
            const ull* xp = (const ull*)&Xs[cc][tw * 8];
            ull x0 = xp[0], x1 = xp[1], x2 = xp[2], x3 = xp[3];
            float4 wv = *(const float4*)&Wt[cc][to * 4];
            ull wd[4] = {dup2(wv.x), dup2(wv.y), dup2(wv.z), dup2(wv.w)};
            #pragma unroll
            for (int j = 0; j < 4; j++) {
                ffma2(acc2[j][0], wd[j], x0);
                ffma2(acc2[j][1], wd[j], x1);
                ffma2(acc2[j][2], wd[j], x2);
                ffma2(acc2[j][3], wd[j], x3);
            }
        }
        __syncthreads();
    }

    #pragma unroll
    for (int j = 0; j < 4; j++) {
        int o = o0 + to * 4 + j;
        float bs = (o < 32) ? bq[o] : (o < 64) ? bk[o - 32] : bv[o - 64];
        #pragma unroll
        for (int i2 = 0; i2 < 4; i2++) {
            float2 f = u2f(acc2[j][i2]);
            Ot[tw * 8 + 2 * i2][to * 4 + j]     = f.x + bs;
            Ot[tw * 8 + 2 * i2 + 1][to * 4 + j] = f.y + bs;
        }
    }
    __syncthreads();

    if (ot == 0) {
        int w = t >> 1, half = t & 1;
        const float* src = &Ot[w][half * 32];
        if (b > 0) {
            float* dst = half ? (g_kH + (((size_t)(b * 128 + w)) * 128 + h) * 32)
                              : (g_qH + (((size_t)(b * 128 + w)) * 128 + h) * 32);
            #pragma unroll
            for (int i = 0; i < 8; i++) ((float4*)dst)[i] = ((const float4*)src)[i];
            float* dq = g_qW + ((size_t)(b * 128 + h)) * 4096;
            float* dk = g_kW + ((size_t)(b * 128 + h)) * 4096;
            #pragma unroll
            for (int r = 0; r < 4; r++) {
                int e = (t + r * 256) << 2;
                int wI = e >> 5, cI = e & 31;
                *(float4*)(dq + e) = *(const float4*)&Ot[wI][cI];
                *(float4*)(dk + e) = *(const float4*)&Ot[wI][32 + cI];
            }
        } else {
            float* dst = g_p0 + ((size_t)(h * 128 + w)) * 320 + half * 32;
            #pragma unroll
            for (int i = 0; i < 8; i++) ((float4*)dst)[i] = ((const float4*)src)[i];
        }
    } else {
        const int c0v = (ot - 1) * 64;
        int w = t >> 1, half = t & 1;
        const float* src = &Ot[w][half * 32];
        if (b > 0) {
            float* dst = g_vH + (((size_t)(b * 128 + w)) * 128 + h) * 256 + c0v + half * 32;
            #pragma unroll
            for (int i = 0; i < 8; i++) ((float4*)dst)[i] = ((const float4*)src)[i];
            float* dw = g_vW + ((size_t)(b * 128 + h)) * 32768 + c0v;
            #pragma unroll
            for (int r = 0; r < 8; r++) {
                int e = (t + r * 256) << 2;
                int wI = e >> 6, cI = e & 63;
                *(float4*)(dw + (size_t)wI * 256 + cI) = *(const float4*)&Ot[wI][cI];
            }
        } else {
            float* dst = g_p0 + ((size_t)(h * 128 + w)) * 320 + 64 + c0v + half * 32;
            #pragma unroll
            for (int i = 0; i < 8; i++) ((float4*)dst)[i] = ((const float4*)src)[i];
        }
    }
}

// ---- deformable bilinear sampling of batch-0 lines: grid (16384, 2), block 320 ----
__global__ void kern_sample()
{
    const int pt = blockIdx.x, br = blockIdx.y;
    const int k = pt >> 7, pos = pt & 127;
    float px, py;
    if (br == 0) {
        int r = pos + 1;
        px = (-1.0f + k * 0.015625f) + g_dX[r][0];
        py = (-1.0f + r * 0.015625f) + g_dX[r][1];
    } else {
        int ci = pos + 1;
        px = (-1.0f + ci * 0.015625f) + g_dY[ci][0];
        py = (-1.0f + k * 0.015625f) + g_dY[ci][1];
    }
    float fx = (px + 1.0f) * 0.5f * 127.0f;
    float fy = (py + 1.0f) * 0.5f * 127.0f;
    float x0f = floorf(fx), y0f = floorf(fy);
    float wx = fx - x0f, wy = fy - y0f;
    int x0 = (int)x0f, y0 = (int)y0f;
    bool vx0 = (x0 >= 0) && (x0 < 128);
    bool vx1 = (x0 + 1 >= 0) && (x0 + 1 < 128);
    bool vy0 = (y0 >= 0) && (y0 < 128);
    bool vy1 = (y0 + 1 >= 0) && (y0 + 1 < 128);

    const int c = threadIdx.x;
    float acc = 0.f;
    if (vx0 && vy0) acc += g_p0[((size_t)(y0 * 128 + x0)) * 320 + c] * ((1.f - wx) * (1.f - wy));
    if (vx1 && vy0) acc += g_p0[((size_t)(y0 * 128 + x0 + 1)) * 320 + c] * (wx * (1.f - wy));
    if (vx0 && vy1) acc += g_p0[((size_t)((y0 + 1) * 128 + x0)) * 320 + c] * ((1.f - wx) * wy);
    if (vx1 && vy1) acc += g_p0[((size_t)((y0 + 1) * 128 + x0 + 1)) * 320 + c] * (wx * wy);

    size_t lp = (size_t)k * 128 + pos;
    if (br == 0) {
        if (c < 32)      g_qH[lp * 32 + c] = acc;
        else if (c < 64) g_kH[lp * 32 + (c - 32)] = acc;
        else             g_vH[lp * 256 + (c - 64)] = acc;
    } else {
        if (c < 32)      g_qW[lp * 32 + c] = acc;
        else if (c < 64) g_kW[lp * 32 + (c - 32)] = acc;
        else             g_vW[lp * 256 + (c - 64)] = acc;
    }
}

// ---- per-line energy GEMM E = Q @ K^T: grid (512, 2), block 256 ----
__global__ __launch_bounds__(256) void kern_energy()
{
    __shared__ __align__(16) float Qt[32][132];
    __shared__ __align__(16) float Kt[32][132];
    const int l = blockIdx.x, br = blockIdx.y;
    const float* Q = (br ? g_qW : g_qH) + (size_t)l * 4096;
    const float* K = (br ? g_kW : g_kH) + (size_t)l * 4096;
    float* E = (br ? g_EW : g_EH) + (size_t)l * 16384;
    const int t = threadIdx.x;

    #pragma unroll
    for (int r = 0; r < 4; r++) {
        int lin = t + r * 256;
        int p = lin >> 3, c4 = (lin & 7) << 2;
        float4 q = *(const float4*)(Q + (size_t)p * 32 + c4);
        Qt[c4][p] = q.x; Qt[c4 + 1][p] = q.y; Qt[c4 + 2][p] = q.z; Qt[c4 + 3][p] = q.w;
        float4 kk = *(const float4*)(K + (size_t)p * 32 + c4);
        Kt[c4][p] = kk.x; Kt[c4 + 1][p] = kk.y; Kt[c4 + 2][p] = kk.z; Kt[c4 + 3][p] = kk.w;
    }
    __syncthreads();

    const int tj = t & 15, ti = t >> 4;
    const int i0 = ti * 8, j0 = tj * 8;
    ull acc2[8][4];
    #pragma unroll
    for (int u = 0; u < 8; u++)
        #pragma unroll
        for (int v = 0; v < 4; v++) acc2[u][v] = 0ULL;

    #pragma unroll
    for (int c = 0; c < 32; c++) {
        float4 qa = *(const float4*)&Qt[c][i0];
        float4 qb = *(const float4*)&Qt[c][i0 + 4];
        ull ad[8] = {dup2(qa.x), dup2(qa.y), dup2(qa.z), dup2(qa.w),
                     dup2(qb.x), dup2(qb.y), dup2(qb.z), dup2(qb.w)};
        const ull* kp = (const ull*)&Kt[c][j0];
        ull b0 = kp[0], b1 = kp[1], b2 = kp[2], b3 = kp[3];
        #pragma unroll
        for (int u = 0; u < 8; u++) {
            ffma2(acc2[u][0], ad[u], b0);
            ffma2(acc2[u][1], ad[u], b1);
            ffma2(acc2[u][2], ad[u], b2);
            ffma2(acc2[u][3], ad[u], b3);
        }
    }
    #pragma unroll
    for (int u = 0; u < 8; u++) {
        float2 p0 = u2f(acc2[u][0]), p1 = u2f(acc2[u][1]);
        float2 p2 = u2f(acc2[u][2]), p3 = u2f(acc2[u][3]);
        *(float4*)(E + (size_t)(i0 + u) * 128 + j0)     = make_float4(p0.x, p0.y, p1.x, p1.y);
        *(float4*)(E + (size_t)(i0 + u) * 128 + j0 + 4) = make_float4(p2.x, p2.y, p3.x, p3.y);
    }
}

// ---- joint softmax: one warp per pixel, grid 8192 x 256 ----
__global__ void kern_softmax()
{
    int gw = (blockIdx.x * blockDim.x + threadIdx.x) >> 5;
    int lane = threadIdx.x & 31;
    if (gw >= 65536) return;
    int b = gw >> 14;
    int rem = gw & 16383;
    int h = rem >> 7, w = rem & 127;
    float* r1 = g_EH + (((size_t)(b * 128 + w)) * 128 + h) * 128;
    float* r2 = g_EW + (((size_t)(b * 128 + h)) * 128 + w) * 128;
    float4 a = *(float4*)(r1 + lane * 4);
    float4 c = *(float4*)(r2 + lane * 4);
    float e1[4] = {a.x, a.y, a.z, a.w};
    float e2[4] = {c.x, c.y, c.z, c.w};
    float m = -INFINITY;
    #pragma unroll
    for (int u = 0; u < 4; u++) {
        if (lane * 4 + u != h) m = fmaxf(m, e1[u]);
        m = fmaxf(m, e2[u]);
    }
    #pragma unroll
    for (int s = 16; s > 0; s >>= 1) m = fmaxf(m, __shfl_xor_sync(0xffffffffu, m, s));
    float sum = 0.f;
    #pragma unroll
    for (int u = 0; u < 4; u++) {
        e1[u] = (lane * 4 + u == h) ? 0.f : __expf(e1[u] - m);
        sum += e1[u];
        e2[u] = __expf(e2[u] - m);
        sum += e2[u];
    }
    #pragma unroll
    for (int s = 16; s > 0; s >>= 1) sum += __shfl_xor_sync(0xffffffffu, sum, s);
    float inv = 1.0f / sum;
    *(float4*)(r1 + lane * 4) = make_float4(e1[0] * inv, e1[1] * inv, e1[2] * inv, e1[3] * inv);
    *(float4*)(r2 + lane * 4) = make_float4(e2[0] * inv, e2[1] * inv, e2[2] * inv, e2[3] * inv);
}

// ---- per-line output GEMM O = A @ V: grid (512, 2 chalf, 2 br), block 256 ----
__global__ __launch_bounds__(256) void kern_out()
{
    __shared__ __align__(16) float As[32][132];
    __shared__ __align__(16) float Vs[32][132];
    const int l = blockIdx.x, chf = blockIdx.y, br = blockIdx.z;
    const float* A = (br ? g_EW : g_EH) + (size_t)l * 16384;
    const float* V = (br ? g_vW : g_vH) + (size_t)l * 32768;
    float* O = (br ? g_rO : g_cO) + (size_t)l * 32768 + chf * 128;
    const int t = threadIdx.x;
    const int tj = t & 15, ti = t >> 4;
    const int i0 = ti * 8, j0 = tj * 8;

    ull acc2[8][4];
    #pragma unroll
    for (int u = 0; u < 8; u++)
        #pragma unroll
        for (int v = 0; v < 4; v++) acc2[u][v] = 0ULL;

    for (int hc = 0; hc < 4; hc++) {
        #pragma unroll
        for (int r = 0; r < 4; r++) {
            int lin = t + r * 256;
            int k = lin >> 3, h4 = (lin & 7) << 2;
            float4 a = *(const float4*)(A + (size_t)k * 128 + hc * 32 + h4);
            As[h4][k] = a.x; As[h4 + 1][k] = a.y; As[h4 + 2][k] = a.z; As[h4 + 3][k] = a.w;
            int hh = lin >> 5, c4 = (lin & 31) << 2;
            *(float4*)&Vs[hh][c4] = *(const float4*)(V + (size_t)(hc * 32 + hh) * 256 + chf * 128 + c4);
        }
        __syncthreads();
        #pragma unroll
        for (int hh = 0; hh < 32; hh++) {
            float4 aa = *(const float4*)&As[hh][i0];
            float4 ab = *(const float4*)&As[hh][i0 + 4];
            ull ad[8] = {dup2(aa.x), dup2(aa.y), dup2(aa.z), dup2(aa.w),
                         dup2(ab.x), dup2(ab.y), dup2(ab.z), dup2(ab.w)};
            const ull* vp = (const ull*)&Vs[hh][j0];
            ull b0 = vp[0], b1 = vp[1], b2 = vp[2], b3 = vp[3];
            #pragma unroll
            for (int u = 0; u < 8; u++) {
                ffma2(acc2[u][0], ad[u], b0);
                ffma2(acc2[u][1], ad[u], b1);
                ffma2(acc2[u][2], ad[u], b2);
                ffma2(acc2[u][3], ad[u], b3);
            }
        }
        __syncthreads();
    }
    #pragma unroll
    for (int u = 0; u < 8; u++) {
        float2 p0 = u2f(acc2[u][0]), p1 = u2f(acc2[u][1]);
        float2 p2 = u2f(acc2[u][2]), p3 = u2f(acc2[u][3]);
        *(float4*)(O + (size_t)(i0 + u) * 256 + j0)     = make_float4(p0.x, p0.y, p1.x, p1.y);
        *(float4*)(O + (size_t)(i0 + u) * 256 + j0 + 4) = make_float4(p2.x, p2.y, p3.x, p3.y);
    }
}

// ---- combine: out = gamma*(colO + rowO) + x: grid (128 h, 8 ctile, 4 b), block 256 ----
__global__ void kern_combine(const float* __restrict__ x, const float* __restrict__ gamma,
                             float* __restrict__ out)
{
    __shared__ __align__(16) float s[32][132];
    const int h = blockIdx.x, ct = blockIdx.y, b = blockIdx.z;
    const int c0 = ct * 32, t = threadIdx.x;
    #pragma unroll
    for (int r = 0; r < 4; r++) {
        int lin = t + r * 256;
        int w = lin >> 3, c4 = (lin & 7) << 2;
        float4 a = *(const float4*)(g_cO + (((size_t)(b * 128 + w)) * 128 + h) * 256 + c0 + c4);
        float4 bb = *(const float4*)(g_rO + (((size_t)(b * 128 + h)) * 128 + w) * 256 + c0 + c4);
        s[c4][w] = a.x + bb.x; s[c4 + 1][w] = a.y + bb.y;
        s[c4 + 2][w] = a.z + bb.z; s[c4 + 3][w] = a.w + bb.w;
    }
    __syncthreads();
    float g = gamma[0];
    #pragma unroll
    for (int r = 0; r < 4; r++) {
        int lin = t + r * 256;
        int c = lin >> 5, w4 = (lin & 31) << 2;
        size_t oidx = (((size_t)b * 256 + c0 + c) * 128 + h) * 128 + w4;
        float4 xv = *(const float4*)(x + oidx);
        float4 o;
        o.x = g * s[c][w4] + xv.x;
        o.y = g * s[c][w4 + 1] + xv.y;
        o.z = g * s[c][w4 + 2] + xv.z;
        o.w = g * s[c][w4 + 3] + xv.w;
        *(float4*)(out + oidx) = o;
    }
}

extern "C" void kernel_launch(void* const* d_in, const int* in_sizes, int n_in,
                              void* d_out, int out_size)
{
    const float* x      = (const float*)d_in[0];
    const float* Wq     = (const float*)d_in[1];
    const float* bq     = (const float*)d_in[2];
    const float* Wk     = (const float*)d_in[3];
    const float* bk     = (const float*)d_in[4];
    const float* Wv     = (const float*)d_in[5];
    const float* bv     = (const float*)d_in[6];
    const float* gamma  = (const float*)d_in[7];
    const float* offs   = (const float*)d_in[8];
    float* out = (float*)d_out;

    kern_prep<<<1, 512>>>(offs, out, out_size - 1);
    kern_proj<<<dim3(128, 5, 4), 256>>>(x, Wq, bq, Wk, bk, Wv, bv);
    kern_sample<<<dim3(16384, 2), 320>>>();
    kern_energy<<<dim3(512, 2), 256>>>();
    kern_softmax<<<8192, 256>>>();
    kern_out<<<dim3(512, 2, 2), 256>>>();
    kern_combine<<<dim3(128, 8, 4), 256>>>(x, gamma, out);
}